// round 11
// baseline (speedup 1.0000x reference)
#include <cuda_runtime.h>
#include <math.h>

#define NB 8
#define NM 64
#define NP (NM / 2)                  // 32 box pairs
#define NA 49104
#define NC 80
#define THREADS 256
#define APB 512                      // anchors per assign block (2 per thread)
#define NA_TILES 96                  // ceil(NA / 512)
#define NAB (NA_TILES * NB)          // 768 assign blocks
#define NSPI 148                     // stream blocks per image
#define NSB (NSPI * NB)              // 1184 stream blocks
#define TOTB (NAB + NSB)             // 1952
#define VEC (NA * (NC / 4))          // float4s per image = 982080
#define SSTRIDE (NSPI * THREADS)
#define KNEG (-0.75f * 0.69314718055994530942f)   // -0.75*ln2 (lg2-domain scale)
#define PMAX (1.0f - 1e-4f)

// global accumulators (zero at module load; last block resets for next replay)
__device__ double       g_cls[NB];
__device__ double       g_reg[NB];
__device__ int          g_npos[NB];
__device__ unsigned int g_done = 0;

__device__ __forceinline__ void commit(float c, float r, int p, int b,
                                       float* s_c, float* s_r, int* s_p,
                                       float* __restrict__ out) {
    #pragma unroll
    for (int o = 16; o; o >>= 1) {
        c += __shfl_down_sync(0xFFFFFFFFu, c, o);
        r += __shfl_down_sync(0xFFFFFFFFu, r, o);
        p += __shfl_down_sync(0xFFFFFFFFu, p, o);
    }
    const int wid = threadIdx.x >> 5, lid = threadIdx.x & 31;
    if (lid == 0) { s_c[wid] = c; s_r[wid] = r; s_p[wid] = p; }
    __syncthreads();
    if (wid == 0) {
        const int nw = THREADS / 32;
        c = (lid < nw) ? s_c[lid] : 0.0f;
        r = (lid < nw) ? s_r[lid] : 0.0f;
        p = (lid < nw) ? s_p[lid] : 0;
        #pragma unroll
        for (int o = 16; o; o >>= 1) {
            c += __shfl_down_sync(0xFFFFFFFFu, c, o);
            r += __shfl_down_sync(0xFFFFFFFFu, r, o);
            p += __shfl_down_sync(0xFFFFFFFFu, p, o);
        }
        if (lid == 0) {
            atomicAdd(&g_cls[b], (double)c);
            if (r != 0.0f) atomicAdd(&g_reg[b], (double)r);
            if (p)         atomicAdd(&g_npos[b], p);
            __threadfence();
            unsigned int ticket = atomicAdd(&g_done, 1u);
            if (ticket == (unsigned int)(TOTB - 1)) {
                double cs = 0.0, rs = 0.0;
                #pragma unroll
                for (int i = 0; i < NB; i++) {
                    double gc = atomicAdd(&g_cls[i], 0.0);   // atomic read
                    double gr = atomicAdd(&g_reg[i], 0.0);
                    int    np = atomicAdd(&g_npos[i], 0);
                    double den = (double)(np > 1 ? np : 1);
                    cs += gc / den;
                    rs += (np > 0) ? (gr / (4.0 * den)) : 0.0;
                    g_cls[i] = 0.0; g_reg[i] = 0.0; g_npos[i] = 0;
                }
                out[0] = (float)(cs / (double)NB);
                out[1] = (float)(rs / (double)NB * 50.0);
                __threadfence();
                g_done = 0;
            }
        }
    }
}

// finalize one anchor's winner: exact ua/divide, thresholds, reg loss, cls correction
__device__ __forceinline__ void anchor_finish(
    float bI, float bS, int bidx,
    float ax1, float ay1, float ax2, float ay2,
    int b, int a,
    const float* __restrict__ cls, const float* __restrict__ reg,
    const float4* s_box, const int* s_lab,
    float& my_cls, float& my_reg, int& my_pos)
{
    float ua = fmaxf(bS - bI, 1e-8f);          // reference's exact ua
    float iou_max = bI / ua;                   // one IEEE divide per anchor

    float4 ab = s_box[bidx];
    float  bw = ab.z - ab.x, bh = ab.w - ab.y;
    bool   big = (bw * bh) > 100.0f;
    bool   pos = big ? (iou_max >= 0.5f) : (iou_max >= 0.15f);
    if (!pos) return;

    my_pos += 1;
    float gcx = ab.x + 0.5f * bw, gcy = ab.y + 0.5f * bh;
    float gw = fmaxf(bw, 1.0f), gh = fmaxf(bh, 1.0f);
    float aw = ax2 - ax1, ah = ay2 - ay1;
    float acx = ax1 + 0.5f * aw, acy = ay1 + 0.5f * ah;
    float tt0 = (gcy - acy) / ah;
    float tt1 = (gcx - acx) / aw;
    float tt2 = logf(gh / ah);
    float tt3 = logf(gw / aw);
    float4 r = ((const float4*)reg)[(size_t)b * NA + a];
    float d;
    d = fabsf(tt0 - r.x); my_reg += (d <= 1.0f/9.0f) ? 4.5f*d*d : d - 0.5f/9.0f;
    d = fabsf(tt1 - r.y); my_reg += (d <= 1.0f/9.0f) ? 4.5f*d*d : d - 0.5f/9.0f;
    d = fabsf(tt2 - r.z); my_reg += (d <= 1.0f/9.0f) ? 4.5f*d*d : d - 0.5f/9.0f;
    d = fabsf(tt3 - r.w); my_reg += (d <= 1.0f/9.0f) ? 4.5f*d*d : d - 0.5f/9.0f;

    // cls correction: + reference positive term, − exactly the neg term the stream added
    int al = s_lab[bidx] - 1;                  // in [0, NC)
    float v = cls[((size_t)b * NA + a) * NC + al];
    float ps = fminf(v, PMAX);                 // stream's p (upper clamp only)
    float neg_term = KNEG * (ps * ps) * __log2f(1.0f - ps);
    float p = fminf(fmaxf(v, 1e-4f), PMAX);
    float om = 1.0f - p;
    my_cls += 0.25f * om * om * (-__logf(p)) - neg_term;
}

__global__ __launch_bounds__(THREADS)
void fl_kernel(const float* __restrict__ boxes,      // [B,M,4] (x1,y1,x2,y2)
               const int*   __restrict__ labels,     // [B,M]
               const float* __restrict__ anchors,    // [1,A,4] (y1,x1,y2,x2)
               const float* __restrict__ cls,        // [B,A,C]
               const float* __restrict__ reg,        // [B,A,4]
               float*       __restrict__ out)        // [2]
{
    __shared__ float4 s_box[NM];
    __shared__ int    s_lab[NM];
    __shared__ float4 s_zx[NP];   // (z_e, z_o, -x_e, -x_o)
    __shared__ float4 s_wy[NP];   // (w_e, w_o, -y_e, -y_o)
    __shared__ float2 s_ba[NP];   // (barea_e, barea_o)
    __shared__ float  s_c[THREADS / 32];
    __shared__ float  s_r[THREADS / 32];
    __shared__ int    s_p[THREADS / 32];

    const int gid = blockIdx.x;
    const int t   = threadIdx.x;

    // 2 assign : 3 stream per 5-block period (768 assign, 1184 stream)
    int role, idx;
    if (gid >= 1920) { role = 1; idx = 1152 + (gid - 1920); }
    else {
        int p5 = gid / 5, r5 = gid - p5 * 5;
        if (r5 < 2) { role = 0; idx = p5 * 2 + r5; }
        else        { role = 1; idx = p5 * 3 + (r5 - 2); }
    }

    if (role == 1) {
        // ===== STREAM: negative focal term, lg2 domain, upper clamp only =====
        const int b   = idx / NSPI;
        const int blk = idx - b * NSPI;
        const float4* __restrict__ cp = (const float4*)(cls + (size_t)b * NA * NC);
        const int tid = blk * THREADS + t;

        float s0 = 0.0f, s1 = 0.0f, s2 = 0.0f, s3 = 0.0f;
        #pragma unroll 8
        for (int i = tid; i < VEC; i += SSTRIDE) {
            float4 v = cp[i];
            float p0 = fminf(v.x, PMAX);           // lower clamp dropped: |err| < 1e-12/elem
            float p1 = fminf(v.y, PMAX);
            float p2 = fminf(v.z, PMAX);
            float p3 = fminf(v.w, PMAX);
            s0 = fmaf(p0 * p0, __log2f(1.0f - p0), s0);
            s1 = fmaf(p1 * p1, __log2f(1.0f - p1), s1);
            s2 = fmaf(p2 * p2, __log2f(1.0f - p2), s2);
            s3 = fmaf(p3 * p3, __log2f(1.0f - p3), s3);
        }
        float csum = KNEG * ((s0 + s1) + (s2 + s3));
        commit(csum, 0.0f, 0, b, s_c, s_r, s_p, out);
        return;
    }

    // ===== ASSIGN: 2 anchors/thread, scalar IoU over packed pairs, exact ratio argmax =====
    const int b     = idx / NA_TILES;
    const int tile  = idx - b * NA_TILES;
    const int abase = tile * APB;

    if (t < NM) {
        float4 bx = ((const float4*)boxes)[b * NM + t];
        int lab   = labels[b * NM + t];
        if (lab == 0)                            // degenerate: inter clamps to 0
            bx = make_float4(3e9f, 3e9f, -3e9f, -3e9f);
        s_box[t] = bx;
        s_lab[t] = lab;
    }
    if (t < NP) {                                // pack pair q = t (boxes 2q, 2q+1)
        float4 e = ((const float4*)boxes)[b * NM + 2 * t];
        float4 o = ((const float4*)boxes)[b * NM + 2 * t + 1];
        int le = labels[b * NM + 2 * t], lo = labels[b * NM + 2 * t + 1];
        float bae, bao;
        if (le == 0) { e = make_float4(3e9f, 3e9f, -3e9f, -3e9f); bae = 0.0f; }
        else bae = (e.z - e.x) * (e.w - e.y);
        if (lo == 0) { o = make_float4(3e9f, 3e9f, -3e9f, -3e9f); bao = 0.0f; }
        else bao = (o.z - o.x) * (o.w - o.y);
        s_zx[t] = make_float4(e.z, o.z, -e.x, -o.x);
        s_wy[t] = make_float4(e.w, o.w, -e.y, -o.y);
        s_ba[t] = make_float2(bae, bao);
    }
    __syncthreads();

    const int aA = abase + t;
    const int aB = abase + t + THREADS;
    const bool vA = (aA < NA), vB = (aB < NA);

    // anchor A constants
    float4 anA = vA ? ((const float4*)anchors)[aA] : make_float4(0,0,0,0);
    const float ay1A = anA.x, ax1A = anA.y, ay2A = anA.z, ax2A = anA.w;
    const float nax1A = -ax1A, nay1A = -ay1A;
    const float areaA = (ay2A - ay1A) * (ax2A - ax1A);
    // anchor B constants
    float4 anB = vB ? ((const float4*)anchors)[aB] : make_float4(0,0,0,0);
    const float ay1B = anB.x, ax1B = anB.y, ay2B = anB.z, ax2B = anB.w;
    const float nax1B = -ax1B, nay1B = -ay1B;
    const float areaB = (ay2B - ay1B) * (ax2B - ax1B);

    float my_reg = 0.0f, my_cls = 0.0f;
    int   my_pos = 0;

    // 2-chain argmax per anchor (lo=even boxes, hi=odd boxes); exact cross-mult compare
    float AI0 = -1.0f, AS0 = 1.0f; int Aq0 = 0;
    float AI1 = -1.0f, AS1 = 1.0f; int Aq1 = 0;
    float BI0 = -1.0f, BS0 = 1.0f; int Bq0 = 0;
    float BI1 = -1.0f, BS1 = 1.0f; int Bq1 = 0;

    #pragma unroll 8
    for (int q = 0; q < NP; q++) {
        float4 zx = s_zx[q];                 // z_e,z_o,-x_e,-x_o
        float4 wy = s_wy[q];                 // w_e,w_o,-y_e,-y_o
        float2 ba = s_ba[q];
        // ---- anchor A ----
        {
            float iw0 = fminf(ax2A, zx.x) + fminf(nax1A, zx.z);
            float iw1 = fminf(ax2A, zx.y) + fminf(nax1A, zx.w);
            float ih0 = fminf(ay2A, wy.x) + fminf(nay1A, wy.z);
            float ih1 = fminf(ay2A, wy.y) + fminf(nay1A, wy.w);
            float I0 = fmaxf(iw0, 0.0f) * fmaxf(ih0, 0.0f);
            float I1 = fmaxf(iw1, 0.0f) * fmaxf(ih1, 0.0f);
            float S0 = areaA + ba.x;
            float S1 = areaA + ba.y;
            if (I0 * AS0 > AI0 * S0) { AI0 = I0; AS0 = S0; Aq0 = q; }
            if (I1 * AS1 > AI1 * S1) { AI1 = I1; AS1 = S1; Aq1 = q; }
        }
        // ---- anchor B ----
        {
            float iw0 = fminf(ax2B, zx.x) + fminf(nax1B, zx.z);
            float iw1 = fminf(ax2B, zx.y) + fminf(nax1B, zx.w);
            float ih0 = fminf(ay2B, wy.x) + fminf(nay1B, wy.z);
            float ih1 = fminf(ay2B, wy.y) + fminf(nay1B, wy.w);
            float I0 = fmaxf(iw0, 0.0f) * fmaxf(ih0, 0.0f);
            float I1 = fmaxf(iw1, 0.0f) * fmaxf(ih1, 0.0f);
            float S0 = areaB + ba.x;
            float S1 = areaB + ba.y;
            if (I0 * BS0 > BI0 * S0) { BI0 = I0; BS0 = S0; Bq0 = q; }
            if (I1 * BS1 > BI1 * S1) { BI1 = I1; BS1 = S1; Bq1 = q; }
        }
    }

    if (vA) {
        float bI = AI0, bS = AS0; int bidx = 2 * Aq0;
        if (AI1 * AS0 > AI0 * AS1) { bI = AI1; bS = AS1; bidx = 2 * Aq1 + 1; }
        anchor_finish(bI, bS, bidx, ax1A, ay1A, ax2A, ay2A, b, aA,
                      cls, reg, s_box, s_lab, my_cls, my_reg, my_pos);
    }
    if (vB) {
        float bI = BI0, bS = BS0; int bidx = 2 * Bq0;
        if (BI1 * BS0 > BI0 * BS1) { bI = BI1; bS = BS1; bidx = 2 * Bq1 + 1; }
        anchor_finish(bI, bS, bidx, ax1B, ay1B, ax2B, ay2B, b, aB,
                      cls, reg, s_box, s_lab, my_cls, my_reg, my_pos);
    }
    commit(my_cls, my_reg, my_pos, b, s_c, s_r, s_p, out);
}

extern "C" void kernel_launch(void* const* d_in, const int* in_sizes, int n_in,
                              void* d_out, int out_size) {
    const float* boxes   = (const float*)d_in[0];
    const int*   labels  = (const int*)  d_in[1];
    const float* anchors = (const float*)d_in[2];
    const float* cls     = (const float*)d_in[3];
    const float* reg     = (const float*)d_in[4];
    float* out = (float*)d_out;

    fl_kernel<<<TOTB, THREADS>>>(boxes, labels, anchors, cls, reg, out);
}

// round 12
// speedup vs baseline: 1.0529x; 1.0529x over previous
#include <cuda_runtime.h>
#include <math.h>

#define NB 8
#define NM 64
#define NP (NM / 2)                  // 32 box pairs
#define NA 49104
#define NC 80
#define THREADS 256
#define NA_TILES 192                 // ceil(NA / 256)
#define NAB (NA_TILES * NB)          // 1536 assign blocks
#define NSPI 148                     // stream blocks per image
#define NSB (NSPI * NB)              // 1184 stream blocks
#define TOTB (NAB + NSB)             // 2720
#define VEC (NA * (NC / 4))          // float4s per image = 982080
#define SSTRIDE (NSPI * THREADS)
#define KNEG (-0.75f * 0.69314718055994530942f)   // -0.75*ln2 (lg2-domain scale)
#define PMAX (1.0f - 1e-4f)

// global accumulators (zero at module load; last block resets for next replay)
__device__ double       g_cls[NB];
__device__ double       g_reg[NB];
__device__ int          g_npos[NB];
__device__ unsigned int g_done = 0;

__device__ __forceinline__ void commit(float c, float r, int p, int b,
                                       float* s_c, float* s_r, int* s_p,
                                       float* __restrict__ out) {
    #pragma unroll
    for (int o = 16; o; o >>= 1) {
        c += __shfl_down_sync(0xFFFFFFFFu, c, o);
        r += __shfl_down_sync(0xFFFFFFFFu, r, o);
        p += __shfl_down_sync(0xFFFFFFFFu, p, o);
    }
    const int wid = threadIdx.x >> 5, lid = threadIdx.x & 31;
    if (lid == 0) { s_c[wid] = c; s_r[wid] = r; s_p[wid] = p; }
    __syncthreads();
    if (wid == 0) {
        const int nw = THREADS / 32;
        c = (lid < nw) ? s_c[lid] : 0.0f;
        r = (lid < nw) ? s_r[lid] : 0.0f;
        p = (lid < nw) ? s_p[lid] : 0;
        #pragma unroll
        for (int o = 16; o; o >>= 1) {
            c += __shfl_down_sync(0xFFFFFFFFu, c, o);
            r += __shfl_down_sync(0xFFFFFFFFu, r, o);
            p += __shfl_down_sync(0xFFFFFFFFu, p, o);
        }
        if (lid == 0) {
            atomicAdd(&g_cls[b], (double)c);
            if (r != 0.0f) atomicAdd(&g_reg[b], (double)r);
            if (p)         atomicAdd(&g_npos[b], p);
            __threadfence();
            unsigned int ticket = atomicAdd(&g_done, 1u);
            if (ticket == (unsigned int)(TOTB - 1)) {
                double cs = 0.0, rs = 0.0;
                #pragma unroll
                for (int i = 0; i < NB; i++) {
                    double gc = atomicAdd(&g_cls[i], 0.0);   // atomic read
                    double gr = atomicAdd(&g_reg[i], 0.0);
                    int    np = atomicAdd(&g_npos[i], 0);
                    double den = (double)(np > 1 ? np : 1);
                    cs += gc / den;
                    rs += (np > 0) ? (gr / (4.0 * den)) : 0.0;
                    g_cls[i] = 0.0; g_reg[i] = 0.0; g_npos[i] = 0;
                }
                out[0] = (float)(cs / (double)NB);
                out[1] = (float)(rs / (double)NB * 50.0);
                __threadfence();
                g_done = 0;
            }
        }
    }
}

__global__ __launch_bounds__(THREADS, 8)   // force <=32 regs -> 8 blocks/SM
void fl_kernel(const float* __restrict__ boxes,      // [B,M,4] (x1,y1,x2,y2)
               const int*   __restrict__ labels,     // [B,M]
               const float* __restrict__ anchors,    // [1,A,4] (y1,x1,y2,x2)
               const float* __restrict__ cls,        // [B,A,C]
               const float* __restrict__ reg,        // [B,A,4]
               float*       __restrict__ out)        // [2]
{
    __shared__ float4 s_box[NM];
    __shared__ int    s_lab[NM];
    __shared__ float4 s_zx[NP];   // (z_e, z_o, -x_e, -x_o)
    __shared__ float4 s_wy[NP];   // (w_e, w_o, -y_e, -y_o)
    __shared__ float2 s_ba[NP];   // (barea_e, barea_o)
    __shared__ float  s_c[THREADS / 32];
    __shared__ float  s_r[THREADS / 32];
    __shared__ int    s_p[THREADS / 32];

    const int gid = blockIdx.x;
    const int t   = threadIdx.x;

    // interleave roles so assign (issue-bound) and stream (DRAM-bound) co-reside
    int role, idx;
    if (gid < 2 * NSB) { role = gid & 1; idx = gid >> 1; }
    else               { role = 0;       idx = NSB + (gid - 2 * NSB); }

    if (role == 1) {
        // ===== STREAM: negative focal term, lg2 domain, upper clamp only =====
        const int b   = idx / NSPI;
        const int blk = idx - b * NSPI;
        const float4* __restrict__ cp = (const float4*)(cls + (size_t)b * NA * NC);
        const int tid = blk * THREADS + t;

        float s0 = 0.0f, s1 = 0.0f, s2 = 0.0f, s3 = 0.0f;
        #pragma unroll 8
        for (int i = tid; i < VEC; i += SSTRIDE) {
            float4 v = cp[i];
            float p0 = fminf(v.x, PMAX);           // lower clamp dropped: |err| < 1e-12/elem
            float p1 = fminf(v.y, PMAX);
            float p2 = fminf(v.z, PMAX);
            float p3 = fminf(v.w, PMAX);
            s0 = fmaf(p0 * p0, __log2f(1.0f - p0), s0);
            s1 = fmaf(p1 * p1, __log2f(1.0f - p1), s1);
            s2 = fmaf(p2 * p2, __log2f(1.0f - p2), s2);
            s3 = fmaf(p3 * p3, __log2f(1.0f - p3), s3);
        }
        float csum = KNEG * ((s0 + s1) + (s2 + s3));
        commit(csum, 0.0f, 0, b, s_c, s_r, s_p, out);
        return;
    }

    // ===== ASSIGN: scalar IoU over packed pairs + exact ratio argmax =====
    const int b    = idx / NA_TILES;
    const int tile = idx - b * NA_TILES;

    if (t < NM) {
        float4 bx = ((const float4*)boxes)[b * NM + t];
        int lab   = labels[b * NM + t];
        if (lab == 0)                            // degenerate: inter clamps to 0
            bx = make_float4(3e9f, 3e9f, -3e9f, -3e9f);
        s_box[t] = bx;
        s_lab[t] = lab;
    }
    if (t < NP) {                                // pack pair q = t (boxes 2q, 2q+1)
        float4 e = ((const float4*)boxes)[b * NM + 2 * t];
        float4 o = ((const float4*)boxes)[b * NM + 2 * t + 1];
        int le = labels[b * NM + 2 * t], lo = labels[b * NM + 2 * t + 1];
        float bae, bao;
        if (le == 0) { e = make_float4(3e9f, 3e9f, -3e9f, -3e9f); bae = 0.0f; }
        else bae = (e.z - e.x) * (e.w - e.y);
        if (lo == 0) { o = make_float4(3e9f, 3e9f, -3e9f, -3e9f); bao = 0.0f; }
        else bao = (o.z - o.x) * (o.w - o.y);
        s_zx[t] = make_float4(e.z, o.z, -e.x, -o.x);
        s_wy[t] = make_float4(e.w, o.w, -e.y, -o.y);
        s_ba[t] = make_float2(bae, bao);
    }
    __syncthreads();

    const int a = tile * THREADS + t;
    float my_reg = 0.0f, my_cls = 0.0f;
    int   my_pos = 0;

    if (a < NA) {
        float4 an = ((const float4*)anchors)[a];   // y1,x1,y2,x2
        const float ay1 = an.x, ax1 = an.y, ay2 = an.z, ax2 = an.w;
        const float nax1 = -ax1, nay1 = -ay1;
        const float a_area = (ay2 - ay1) * (ax2 - ax1);

        // two argmax chains: lo = even boxes (2q), hi = odd (2q+1); exact cross-mult compare
        float bI0 = -1.0f, bS0 = 1.0f; int bq0 = 0;
        float bI1 = -1.0f, bS1 = 1.0f; int bq1 = 0;
        #pragma unroll 8
        for (int q = 0; q < NP; q++) {
            float4 zx = s_zx[q];                 // z_e,z_o,-x_e,-x_o
            float4 wy = s_wy[q];                 // w_e,w_o,-y_e,-y_o
            float2 ba = s_ba[q];
            // iw = min(ax2,z) + min(-ax1,-x) == min(ax2,z) - max(ax1,x)  (exact)
            float iw0 = fminf(ax2, zx.x) + fminf(nax1, zx.z);
            float iw1 = fminf(ax2, zx.y) + fminf(nax1, zx.w);
            float ih0 = fminf(ay2, wy.x) + fminf(nay1, wy.z);
            float ih1 = fminf(ay2, wy.y) + fminf(nay1, wy.w);
            float I0 = fmaxf(iw0, 0.0f) * fmaxf(ih0, 0.0f);
            float I1 = fmaxf(iw1, 0.0f) * fmaxf(ih1, 0.0f);
            float S0 = a_area + ba.x;
            float S1 = a_area + ba.y;
            if (I0 * bS0 > bI0 * S0) { bI0 = I0; bS0 = S0; bq0 = q; }
            if (I1 * bS1 > bI1 * S1) { bI1 = I1; bS1 = S1; bq1 = q; }
        }
        // merge: odd chain wins only with STRICTLY larger ratio (first-max preserved)
        float bI = bI0, bS = bS0; int bidx = 2 * bq0;
        if (bI1 * bS0 > bI0 * bS1) { bI = bI1; bS = bS1; bidx = 2 * bq1 + 1; }

        float ua = fmaxf(bS - bI, 1e-8f);          // reference's exact ua
        float iou_max = bI / ua;                   // one IEEE divide per anchor

        float4 ab = s_box[bidx];
        float  bw = ab.z - ab.x, bh = ab.w - ab.y;
        bool   big = (bw * bh) > 100.0f;
        bool   pos = big ? (iou_max >= 0.5f) : (iou_max >= 0.15f);

        if (pos) {
            my_pos = 1;
            float gcx = ab.x + 0.5f * bw, gcy = ab.y + 0.5f * bh;
            float gw = fmaxf(bw, 1.0f), gh = fmaxf(bh, 1.0f);
            float aw = ax2 - ax1, ah = ay2 - ay1;
            float acx = ax1 + 0.5f * aw, acy = ay1 + 0.5f * ah;
            float tt0 = (gcy - acy) / ah;
            float tt1 = (gcx - acx) / aw;
            float tt2 = logf(gh / ah);
            float tt3 = logf(gw / aw);
            float4 r = ((const float4*)reg)[(size_t)b * NA + a];
            float d;
            d = fabsf(tt0 - r.x); my_reg += (d <= 1.0f/9.0f) ? 4.5f*d*d : d - 0.5f/9.0f;
            d = fabsf(tt1 - r.y); my_reg += (d <= 1.0f/9.0f) ? 4.5f*d*d : d - 0.5f/9.0f;
            d = fabsf(tt2 - r.z); my_reg += (d <= 1.0f/9.0f) ? 4.5f*d*d : d - 0.5f/9.0f;
            d = fabsf(tt3 - r.w); my_reg += (d <= 1.0f/9.0f) ? 4.5f*d*d : d - 0.5f/9.0f;

            // cls correction for the target class:
            //  + reference positive term (full clamp)
            //  - EXACTLY the neg term the stream added (upper clamp only)
            int al = s_lab[bidx] - 1;              // in [0, NC)
            float v = cls[((size_t)b * NA + a) * NC + al];
            float ps = fminf(v, PMAX);             // stream's p (upper clamp only)
            float neg_term = KNEG * (ps * ps) * __log2f(1.0f - ps);
            float p = fminf(fmaxf(v, 1e-4f), PMAX);
            float om = 1.0f - p;
            my_cls = 0.25f * om * om * (-__logf(p)) - neg_term;
        }
    }
    commit(my_cls, my_reg, my_pos, b, s_c, s_r, s_p, out);
}

extern "C" void kernel_launch(void* const* d_in, const int* in_sizes, int n_in,
                              void* d_out, int out_size) {
    const float* boxes   = (const float*)d_in[0];
    const int*   labels  = (const int*)  d_in[1];
    const float* anchors = (const float*)d_in[2];
    const float* cls     = (const float*)d_in[3];
    const float* reg     = (const float*)d_in[4];
    float* out = (float*)d_out;

    fl_kernel<<<TOTB, THREADS>>>(boxes, labels, anchors, cls, reg, out);
}

// round 13
// speedup vs baseline: 1.0936x; 1.0386x over previous
#include <cuda_runtime.h>
#include <math.h>

#define NB 8
#define NM 64
#define NP (NM / 2)                  // 32 box pairs
#define NA 49104
#define NC 80
#define THREADS 256
#define NA_TILES 192                 // ceil(NA / 256)
#define NAB (NA_TILES * NB)          // 1536 assign blocks
#define NSPI 148                     // stream blocks per image
#define NSB (NSPI * NB)              // 1184 stream blocks
#define TOTB (NAB + NSB)             // 2720
#define VEC (NA * (NC / 4))          // float4s per image = 982080
#define SSTRIDE (NSPI * THREADS)
#define KNEG (-0.75f * 0.69314718055994530942f)   // -0.75*ln2 (lg2-domain scale)
#define PMAX (1.0f - 1e-4f)

// global accumulators (zero at module load; last block resets for next replay)
__device__ double       g_cls[NB];
__device__ double       g_reg[NB];
__device__ int          g_npos[NB];
__device__ unsigned int g_done = 0;

__device__ __forceinline__ void commit(float c, float r, int p, int b,
                                       float* s_c, float* s_r, int* s_p,
                                       float* __restrict__ out) {
    #pragma unroll
    for (int o = 16; o; o >>= 1) {
        c += __shfl_down_sync(0xFFFFFFFFu, c, o);
        r += __shfl_down_sync(0xFFFFFFFFu, r, o);
        p += __shfl_down_sync(0xFFFFFFFFu, p, o);
    }
    const int wid = threadIdx.x >> 5, lid = threadIdx.x & 31;
    if (lid == 0) { s_c[wid] = c; s_r[wid] = r; s_p[wid] = p; }
    __syncthreads();
    if (wid == 0) {
        const int nw = THREADS / 32;
        c = (lid < nw) ? s_c[lid] : 0.0f;
        r = (lid < nw) ? s_r[lid] : 0.0f;
        p = (lid < nw) ? s_p[lid] : 0;
        #pragma unroll
        for (int o = 16; o; o >>= 1) {
            c += __shfl_down_sync(0xFFFFFFFFu, c, o);
            r += __shfl_down_sync(0xFFFFFFFFu, r, o);
            p += __shfl_down_sync(0xFFFFFFFFu, p, o);
        }
        if (lid == 0) {
            atomicAdd(&g_cls[b], (double)c);
            if (r != 0.0f) atomicAdd(&g_reg[b], (double)r);
            if (p)         atomicAdd(&g_npos[b], p);
            __threadfence();
            unsigned int ticket = atomicAdd(&g_done, 1u);
            if (ticket == (unsigned int)(TOTB - 1)) {
                double cs = 0.0, rs = 0.0;
                #pragma unroll
                for (int i = 0; i < NB; i++) {
                    double gc = atomicAdd(&g_cls[i], 0.0);   // atomic read
                    double gr = atomicAdd(&g_reg[i], 0.0);
                    int    np = atomicAdd(&g_npos[i], 0);
                    double den = (double)(np > 1 ? np : 1);
                    cs += gc / den;
                    rs += (np > 0) ? (gr / (4.0 * den)) : 0.0;
                    g_cls[i] = 0.0; g_reg[i] = 0.0; g_npos[i] = 0;
                }
                out[0] = (float)(cs / (double)NB);
                out[1] = (float)(rs / (double)NB * 50.0);
                __threadfence();
                g_done = 0;
            }
        }
    }
}

__global__ __launch_bounds__(THREADS)
void fl_kernel(const float* __restrict__ boxes,      // [B,M,4] (x1,y1,x2,y2)
               const int*   __restrict__ labels,     // [B,M]
               const float* __restrict__ anchors,    // [1,A,4] (y1,x1,y2,x2)
               const float* __restrict__ cls,        // [B,A,C]
               const float* __restrict__ reg,        // [B,A,4]
               float*       __restrict__ out)        // [2]
{
    __shared__ float4 s_box[NM];
    __shared__ int    s_lab[NM];
    __shared__ float4 s_zx[NP];   // (z_e, z_o, -x_e, -x_o)
    __shared__ float4 s_wy[NP];   // (w_e, w_o, -y_e, -y_o)
    __shared__ float2 s_ba[NP];   // (barea_e, barea_o)
    __shared__ float  s_c[THREADS / 32];
    __shared__ float  s_r[THREADS / 32];
    __shared__ int    s_p[THREADS / 32];

    const int gid = blockIdx.x;
    const int t   = threadIdx.x;

    // interleave roles so assign (issue-bound) and stream (DRAM-bound) co-reside
    int role, idx;
    if (gid < 2 * NSB) { role = gid & 1; idx = gid >> 1; }
    else               { role = 0;       idx = NSB + (gid - 2 * NSB); }

    if (role == 1) {
        // ===== STREAM: negative focal term, lg2 domain, upper clamp only =====
        const int b   = idx / NSPI;
        const int blk = idx - b * NSPI;
        const float4* __restrict__ cp = (const float4*)(cls + (size_t)b * NA * NC);
        const int tid = blk * THREADS + t;

        float s0 = 0.0f, s1 = 0.0f, s2 = 0.0f, s3 = 0.0f;
        #pragma unroll 8
        for (int i = tid; i < VEC; i += SSTRIDE) {
            float4 v = cp[i];
            float p0 = fminf(v.x, PMAX);           // lower clamp dropped: |err| < 1e-12/elem
            float p1 = fminf(v.y, PMAX);
            float p2 = fminf(v.z, PMAX);
            float p3 = fminf(v.w, PMAX);
            s0 = fmaf(p0 * p0, __log2f(1.0f - p0), s0);
            s1 = fmaf(p1 * p1, __log2f(1.0f - p1), s1);
            s2 = fmaf(p2 * p2, __log2f(1.0f - p2), s2);
            s3 = fmaf(p3 * p3, __log2f(1.0f - p3), s3);
        }
        float csum = KNEG * ((s0 + s1) + (s2 + s3));
        commit(csum, 0.0f, 0, b, s_c, s_r, s_p, out);
        return;
    }

    // ===== ASSIGN: MUFU-rcp ratio argmax (r = I/S, monotone in IoU) =====
    const int b    = idx / NA_TILES;
    const int tile = idx - b * NA_TILES;

    if (t < NM) {
        float4 bx = ((const float4*)boxes)[b * NM + t];
        int lab   = labels[b * NM + t];
        if (lab == 0)                            // degenerate: inter clamps to 0
            bx = make_float4(3e9f, 3e9f, -3e9f, -3e9f);
        s_box[t] = bx;
        s_lab[t] = lab;
    }
    if (t < NP) {                                // pack pair q = t (boxes 2q, 2q+1)
        float4 e = ((const float4*)boxes)[b * NM + 2 * t];
        float4 o = ((const float4*)boxes)[b * NM + 2 * t + 1];
        int le = labels[b * NM + 2 * t], lo = labels[b * NM + 2 * t + 1];
        float bae, bao;
        if (le == 0) { e = make_float4(3e9f, 3e9f, -3e9f, -3e9f); bae = 0.0f; }
        else bae = (e.z - e.x) * (e.w - e.y);
        if (lo == 0) { o = make_float4(3e9f, 3e9f, -3e9f, -3e9f); bao = 0.0f; }
        else bao = (o.z - o.x) * (o.w - o.y);
        s_zx[t] = make_float4(e.z, o.z, -e.x, -o.x);
        s_wy[t] = make_float4(e.w, o.w, -e.y, -o.y);
        s_ba[t] = make_float2(bae, bao);
    }
    __syncthreads();

    const int a = tile * THREADS + t;
    float my_reg = 0.0f, my_cls = 0.0f;
    int   my_pos = 0;

    if (a < NA) {
        float4 an = ((const float4*)anchors)[a];   // y1,x1,y2,x2
        const float ay1 = an.x, ax1 = an.y, ay2 = an.z, ax2 = an.w;
        const float nax1 = -ax1, nay1 = -ay1;
        const float a_area = (ay2 - ay1) * (ax2 - ax1);

        // two argmax chains on r = I/S (approx rcp): lo = even boxes, hi = odd boxes
        float br0 = -1.0f; int bq0 = 0;
        float br1 = -1.0f; int bq1 = 0;
        #pragma unroll 8
        for (int q = 0; q < NP; q++) {
            float4 zx = s_zx[q];                 // z_e,z_o,-x_e,-x_o
            float4 wy = s_wy[q];                 // w_e,w_o,-y_e,-y_o
            float2 ba = s_ba[q];
            // iw = min(ax2,z) + min(-ax1,-x) == min(ax2,z) - max(ax1,x)  (exact)
            float iw0 = fminf(ax2, zx.x) + fminf(nax1, zx.z);
            float iw1 = fminf(ax2, zx.y) + fminf(nax1, zx.w);
            float ih0 = fminf(ay2, wy.x) + fminf(nay1, wy.z);
            float ih1 = fminf(ay2, wy.y) + fminf(nay1, wy.w);
            float I0 = fmaxf(iw0, 0.0f) * fmaxf(ih0, 0.0f);
            float I1 = fmaxf(iw1, 0.0f) * fmaxf(ih1, 0.0f);
            float r0 = __fdividef(I0, a_area + ba.x);   // MUFU.RCP + FMUL
            float r1 = __fdividef(I1, a_area + ba.y);
            if (r0 > br0) { br0 = r0; bq0 = q; }
            if (r1 > br1) { br1 = r1; bq1 = q; }
        }
        // merge: odd chain wins only with STRICTLY larger r (first-max preserved)
        int bidx = 2 * bq0;
        if (br1 > br0) bidx = 2 * bq1 + 1;

        // winner: recompute IoU EXACTLY as the reference does
        float4 ab = s_box[bidx];
        float iwx = fminf(ax2, ab.z) - fmaxf(ax1, ab.x);
        float ihx = fminf(ay2, ab.w) - fmaxf(ay1, ab.y);
        iwx = fmaxf(iwx, 0.0f); ihx = fmaxf(ihx, 0.0f);
        float inter = iwx * ihx;
        float barea = (ab.z - ab.x) * (ab.w - ab.y);
        float ua = fmaxf(a_area + barea - inter, 1e-8f);
        float iou_max = inter / ua;                // IEEE divide, once per anchor

        float  bw = ab.z - ab.x, bh = ab.w - ab.y;
        bool   big = (bw * bh) > 100.0f;
        bool   pos = big ? (iou_max >= 0.5f) : (iou_max >= 0.15f);

        if (pos) {
            my_pos = 1;
            float gcx = ab.x + 0.5f * bw, gcy = ab.y + 0.5f * bh;
            float gw = fmaxf(bw, 1.0f), gh = fmaxf(bh, 1.0f);
            float aw = ax2 - ax1, ah = ay2 - ay1;
            float acx = ax1 + 0.5f * aw, acy = ay1 + 0.5f * ah;
            float tt0 = (gcy - acy) / ah;
            float tt1 = (gcx - acx) / aw;
            float tt2 = logf(gh / ah);
            float tt3 = logf(gw / aw);
            float4 r = ((const float4*)reg)[(size_t)b * NA + a];
            float d;
            d = fabsf(tt0 - r.x); my_reg += (d <= 1.0f/9.0f) ? 4.5f*d*d : d - 0.5f/9.0f;
            d = fabsf(tt1 - r.y); my_reg += (d <= 1.0f/9.0f) ? 4.5f*d*d : d - 0.5f/9.0f;
            d = fabsf(tt2 - r.z); my_reg += (d <= 1.0f/9.0f) ? 4.5f*d*d : d - 0.5f/9.0f;
            d = fabsf(tt3 - r.w); my_reg += (d <= 1.0f/9.0f) ? 4.5f*d*d : d - 0.5f/9.0f;

            // cls correction for the target class:
            //  + reference positive term (full clamp)
            //  - EXACTLY the neg term the stream added (upper clamp only)
            int al = s_lab[bidx] - 1;              // in [0, NC)
            float v = cls[((size_t)b * NA + a) * NC + al];
            float ps = fminf(v, PMAX);             // stream's p (upper clamp only)
            float neg_term = KNEG * (ps * ps) * __log2f(1.0f - ps);
            float p = fminf(fmaxf(v, 1e-4f), PMAX);
            float om = 1.0f - p;
            my_cls = 0.25f * om * om * (-__logf(p)) - neg_term;
        }
    }
    commit(my_cls, my_reg, my_pos, b, s_c, s_r, s_p, out);
}

extern "C" void kernel_launch(void* const* d_in, const int* in_sizes, int n_in,
                              void* d_out, int out_size) {
    const float* boxes   = (const float*)d_in[0];
    const int*   labels  = (const int*)  d_in[1];
    const float* anchors = (const float*)d_in[2];
    const float* cls     = (const float*)d_in[3];
    const float* reg     = (const float*)d_in[4];
    float* out = (float*)d_out;

    fl_kernel<<<TOTB, THREADS>>>(boxes, labels, anchors, cls, reg, out);
}